// round 4
// baseline (speedup 1.0000x reference)
#include <cuda_runtime.h>
#include <math.h>

#define H 1024
#define W 1024
#define R 18
#define KS 37           // 2*R+1
#define NSTEP 16
#define VY 8            // output rows per thread in vertical blur
#define VX 8            // output cols per thread in horizontal blur
#define W4 (W/4)
#define INV_N (1.0f/16.0f)

// Persistent scratch (device globals: allowed; no runtime allocation)
// Packed state: .x = z (residual), .y = img
__device__ float2 g_zi[2][H*W];
__device__ float g_f[2][H*W];   // force: fx = -z*gx, fy = -z*gy
__device__ float g_t[2][H*W];   // after vertical blur
__device__ float g_v[2][H*W];   // velocity (vx, vy)

// ---------------------------------------------------------------------------
// Gaussian weights (sigma=6, radius 18), normalized; literals -> FFMA-imm.
__device__ __forceinline__ float wt(int i) {
    int d = i < R ? R - i : i - R;
    switch (d) {
        case 0:  return 0.066625152f;
        case 1:  return 0.065706198f;
        case 2:  return 0.063024692f;
        case 3:  return 0.058796492f;
        case 4:  return 0.053349252f;
        case 5:  return 0.047080544f;
        case 6:  return 0.040410194f;
        case 7:  return 0.033734705f;
        case 8:  return 0.027390419f;
        case 9:  return 0.021630020f;
        case 10: return 0.016613128f;
        case 11: return 0.012410281f;
        case 12: return 0.009016734f;
        case 13: return 0.006371659f;
        case 14: return 0.004379178f;
        case 15: return 0.002927305f;
        case 16: return 0.001903181f;
        case 17: return 0.001203452f;
        case 18: return 0.000740139f;
    }
    return 0.f;
}

__device__ __forceinline__ void fma4(float4& a, float w, const float4& v) {
    a.x += w * v.x; a.y += w * v.y; a.z += w * v.z; a.w += w * v.w;
}
__device__ __forceinline__ float get4(const float4& q, int e) {
    return e == 0 ? q.x : e == 1 ? q.y : e == 2 ? q.z : q.w;
}

// ---------------------------------------------------------------------------
// pack harness inputs into interleaved (z, img) state buffer 0
__global__ void pack_k(const float* __restrict__ image,
                       const float* __restrict__ resid) {
    int i = blockIdx.x * blockDim.x + threadIdx.x;   // pixel pair index
    float2 z2 = ((const float2*)resid)[i];
    float2 i2 = ((const float2*)image)[i];
    float4 o;
    o.x = z2.x; o.y = i2.x; o.z = z2.y; o.w = i2.y;
    ((float4*)g_zi[0])[i] = o;
}

// ---------------------------------------------------------------------------
// force: f = (-z*gx, -z*gy). One thread = 4 pixels (2 packed float4 loads/row).
__global__ __launch_bounds__(128) void force_k(const float2* __restrict__ zi) {
    int p = blockIdx.x * blockDim.x + threadIdx.x;   // pixel-quad index 0..255
    int y = blockIdx.y;
    int x0 = p * 4;
    int ym = max(y - 1, 0), yp = min(y + 1, H - 1);

    const float4* rc = (const float4*)(zi + y  * W);
    const float4* ru = (const float4*)(zi + ym * W);
    const float4* rd = (const float4*)(zi + yp * W);

    // each float4 holds 2 pixels: (z0, i0, z1, i1)
    float4 c01 = rc[p * 2], c23 = rc[p * 2 + 1];
    float4 u01 = ru[p * 2], u23 = ru[p * 2 + 1];
    float4 d01 = rd[p * 2], d23 = rd[p * 2 + 1];

    float iL = (x0 > 0)     ? zi[y * W + x0 - 1].y : c01.y;
    float iR = (x0 + 4 < W) ? zi[y * W + x0 + 4].y : c23.w;

    float z[4]  = {c01.x, c01.z, c23.x, c23.z};
    float ic[4] = {c01.y, c01.w, c23.y, c23.w};
    float iu[4] = {u01.y, u01.w, u23.y, u23.w};
    float id[4] = {d01.y, d01.w, d23.y, d23.w};

    float4 f0, f1;
    f0.x = -z[0] * 0.5f * (ic[1] - iL);
    f0.y = -z[1] * 0.5f * (ic[2] - ic[0]);
    f0.z = -z[2] * 0.5f * (ic[3] - ic[1]);
    f0.w = -z[3] * 0.5f * (iR    - ic[2]);
    f1.x = -z[0] * 0.5f * (id[0] - iu[0]);
    f1.y = -z[1] * 0.5f * (id[1] - iu[1]);
    f1.z = -z[2] * 0.5f * (id[2] - iu[2]);
    f1.w = -z[3] * 0.5f * (id[3] - iu[3]);

    ((float4*)g_f[0])[y * W4 + p] = f0;
    ((float4*)g_f[1])[y * W4 + p] = f1;
}

// ---------------------------------------------------------------------------
// vertical blur: one thread = one float4 column x VY rows x 2 channels
__global__ __launch_bounds__(64, 4) void vblur_k() {
    int c  = blockIdx.x * blockDim.x + threadIdx.x;  // float4 column 0..255
    int y0 = blockIdx.y * VY;

    const float4* __restrict__ f0p = (const float4*)g_f[0];
    const float4* __restrict__ f1p = (const float4*)g_f[1];

    float4 a0[VY], a1[VY];
#pragma unroll
    for (int o = 0; o < VY; o++) {
        a0[o] = make_float4(0.f, 0.f, 0.f, 0.f);
        a1[o] = make_float4(0.f, 0.f, 0.f, 0.f);
    }

#pragma unroll
    for (int j = 0; j < KS + VY - 1; j++) {      // input rows y0-R+j
        int yy = y0 - R + j;
        yy = max(0, min(H - 1, yy));
        float4 f0 = f0p[yy * W4 + c];
        float4 f1 = f1p[yy * W4 + c];
#pragma unroll
        for (int o = 0; o < VY; o++) {
            int tap = j - o;
            if (tap >= 0 && tap < KS) {
                float w = wt(tap);
                fma4(a0[o], w, f0);
                fma4(a1[o], w, f1);
            }
        }
    }
#pragma unroll
    for (int o = 0; o < VY; o++) {
        ((float4*)g_t[0])[(y0 + o) * W4 + c] = a0[o];
        ((float4*)g_t[1])[(y0 + o) * W4 + c] = a1[o];
    }
}

// ---------------------------------------------------------------------------
// horizontal blur: one thread = VX=8 consecutive cols, channels sequential.
__global__ __launch_bounds__(128, 4) void hblur_k() {
    int t  = threadIdx.x;          // 0..127
    int y  = blockIdx.x;           // one row per block
    int x0 = t * VX;

    bool interior = (t >= 3 && t <= 124);

#pragma unroll
    for (int ch = 0; ch < 2; ch++) {
        const float* __restrict__ row = g_t[ch] + y * W;
        float a[VX];
#pragma unroll
        for (int o = 0; o < VX; o++) a[o] = 0.f;

        if (interior) {
            // inputs needed: [x0-18, x0+25]; aligned window [x0-20, x0+28)
            const float4* r = (const float4*)(row + x0 - 20);
#pragma unroll
            for (int c4 = 0; c4 < 12; c4++) {
                float4 q = r[c4];
#pragma unroll
                for (int e = 0; e < 4; e++) {
                    int j = c4 * 4 + e;            // input x = x0-20+j
                    float v = get4(q, e);
#pragma unroll
                    for (int o = 0; o < VX; o++) {
                        int tap = j - 2 - o;        // (x0-20+j) - (x0+o-18)
                        if (tap >= 0 && tap < KS) a[o] += wt(tap) * v;
                    }
                }
            }
        } else {
#pragma unroll
            for (int j = 0; j < KS + VX - 1; j++) { // input x = x0-R+j
                int xx = x0 - R + j;
                xx = max(0, min(W - 1, xx));
                float v = row[xx];
#pragma unroll
                for (int o = 0; o < VX; o++) {
                    int tap = j - o;
                    if (tap >= 0 && tap < KS) a[o] += wt(tap) * v;
                }
            }
        }
        // v = smooth * (RHO/MU), RHO=MU=1
        float4* dst = (float4*)(g_v[ch] + y * W + x0);
        dst[0] = make_float4(a[0], a[1], a[2], a[3]);
        dst[1] = make_float4(a[4], a[5], a[6], a[7]);
    }
}

// ---------------------------------------------------------------------------
// packed bilinear sample (both fields at once) with border clamping
__device__ __forceinline__ float2 bilin2(const float2* __restrict__ a,
                                         float cy, float cx) {
    float fy = floorf(cy), fx = floorf(cx);
    float wy = cy - fy,    wx = cx - fx;
    int y0 = (int)fy, x0 = (int)fx;
    int y0c = min(max(y0, 0), H - 1);
    int y1c = min(max(y0 + 1, 0), H - 1);
    int x0c = min(max(x0, 0), W - 1);
    int x1c = min(max(x0 + 1, 0), W - 1);
    float2 a00 = a[y0c * W + x0c], a01 = a[y0c * W + x1c];
    float2 a10 = a[y1c * W + x0c], a11 = a[y1c * W + x1c];
    float2 t0, t1, r;
    t0.x = a00.x + wx * (a01.x - a00.x);
    t0.y = a00.y + wx * (a01.y - a00.y);
    t1.x = a10.x + wx * (a11.x - a10.x);
    t1.y = a10.y + wx * (a11.y - a10.y);
    r.x = t0.x + wy * (t1.x - t0.x);
    r.y = t0.y + wy * (t1.y - t0.y);
    return r;
}

// divergence + semi-Lagrangian update; one thread = 4 consecutive pixels
__global__ __launch_bounds__(128) void advect_k(const float2* __restrict__ zi,
                                                float2* __restrict__ zo,
                                                float* __restrict__ iout,
                                                int last) {
    int c = blockIdx.x * blockDim.x + threadIdx.x;   // pixel-quad index 0..255
    int y = blockIdx.y;
    int x0 = c * 4;
    int rc = y * W4 + c;

    const float4* __restrict__ vx4 = (const float4*)g_v[0];
    const float4* __restrict__ vy4 = (const float4*)g_v[1];
    int ym = max(y - 1, 0), yp = min(y + 1, H - 1);

    float4 vxc = vx4[rc];
    float4 vyc = vy4[rc];
    float4 vyu = vy4[ym * W4 + c];
    float4 vyd = vy4[yp * W4 + c];
    float vxl = (x0 > 0)     ? g_v[0][y * W + x0 - 1] : vxc.x;
    float vxr = (x0 + 4 < W) ? g_v[0][y * W + x0 + 4] : vxc.w;

    float div[4];
    div[0] = 0.5f * (vxc.y - vxl)   + 0.5f * (vyd.x - vyu.x);
    div[1] = 0.5f * (vxc.z - vxc.x) + 0.5f * (vyd.y - vyu.y);
    div[2] = 0.5f * (vxc.w - vxc.y) + 0.5f * (vyd.z - vyu.z);
    div[3] = 0.5f * (vxr   - vxc.z) + 0.5f * (vyd.w - vyu.w);

    // center packed state (z at .x)
    float4 c01 = ((const float4*)zi)[rc * 2];
    float4 c23 = ((const float4*)zi)[rc * 2 + 1];
    float zoa[4] = {c01.x, c01.z, c23.x, c23.z};

    float vxa[4] = {vxc.x, vxc.y, vxc.z, vxc.w};
    float vya[4] = {vyc.x, vyc.y, vyc.z, vyc.w};
    float zn[4], in_[4];
#pragma unroll
    for (int e = 0; e < 4; e++) {
        float cy = (float)y        - vya[e] * INV_N;
        float cx = (float)(x0 + e) - vxa[e] * INV_N;
        float2 s = bilin2(zi, cy, cx);        // s.x = warped z, s.y = warped img
        zn[e]  = s.x - zoa[e] * div[e] * INV_N;
        in_[e] = s.y + zn[e] * INV_N;          // * MU / N, MU = 1
    }
    ((float4*)zo)[rc * 2]     = make_float4(zn[0], in_[0], zn[1], in_[1]);
    ((float4*)zo)[rc * 2 + 1] = make_float4(zn[2], in_[2], zn[3], in_[3]);
    if (last) {
        ((float4*)iout)[rc] = make_float4(in_[0], in_[1], in_[2], in_[3]);
    }
}

// ---------------------------------------------------------------------------
extern "C" void kernel_launch(void* const* d_in, const int* in_sizes, int n_in,
                              void* d_out, int out_size) {
    const float* image = (const float*)d_in[0];
    const float* resid = (const float*)d_in[1];

    void* p_zi = nullptr;
    cudaGetSymbolAddress(&p_zi, g_zi);
    float2* zibuf[2] = {(float2*)p_zi, (float2*)p_zi + H * W};

    pack_k<<<(H * W / 2) / 256, 256>>>(image, resid);

    dim3 gsP(W4 / 128, H);
    for (int s = 0; s < NSTEP; s++) {
        int cur = s & 1, nxt = cur ^ 1;
        force_k<<<gsP, 128>>>(zibuf[cur]);
        vblur_k<<<dim3(W4 / 64, H / VY), 64>>>();
        hblur_k<<<H, W / VX>>>();
        advect_k<<<gsP, 128>>>(zibuf[cur], zibuf[nxt], (float*)d_out,
                               s == NSTEP - 1 ? 1 : 0);
    }
}

// round 6
// speedup vs baseline: 1.1381x; 1.1381x over previous
#include <cuda_runtime.h>
#include <math.h>

#define H 1024
#define W 1024
#define R 18
#define KS 37           // 2*R+1
#define NSTEP 16
#define VY 8            // output rows per thread in vertical blur
#define VX 8            // output cols per thread in horizontal blur
#define W4 (W/4)
#define INV_N (1.0f/16.0f)

// Persistent scratch (device globals: allowed; no runtime allocation)
__device__ float g_img[2][H*W];
__device__ float g_z[2][H*W];
__device__ float g_f[2][H*W];   // force: fx = -z*gx, fy = -z*gy
__device__ float g_t[2][H*W];   // after vertical blur
__device__ float g_v[2][H*W];   // velocity (vx, vy)

// ---------------------------------------------------------------------------
// Gaussian weights (sigma=6, radius 18), normalized; literals -> FFMA-imm.
__device__ __forceinline__ float wt(int i) {
    int d = i < R ? R - i : i - R;
    switch (d) {
        case 0:  return 0.066625152f;
        case 1:  return 0.065706198f;
        case 2:  return 0.063024692f;
        case 3:  return 0.058796492f;
        case 4:  return 0.053349252f;
        case 5:  return 0.047080544f;
        case 6:  return 0.040410194f;
        case 7:  return 0.033734705f;
        case 8:  return 0.027390419f;
        case 9:  return 0.021630020f;
        case 10: return 0.016613128f;
        case 11: return 0.012410281f;
        case 12: return 0.009016734f;
        case 13: return 0.006371659f;
        case 14: return 0.004379178f;
        case 15: return 0.002927305f;
        case 16: return 0.001903181f;
        case 17: return 0.001203452f;
        case 18: return 0.000740139f;
    }
    return 0.f;
}

__device__ __forceinline__ void fma4(float4& a, float w, const float4& v) {
    a.x += w * v.x; a.y += w * v.y; a.z += w * v.z; a.w += w * v.w;
}
__device__ __forceinline__ float get4(const float4& q, int e) {
    return e == 0 ? q.x : e == 1 ? q.y : e == 2 ? q.z : q.w;
}

// ---------------------------------------------------------------------------
// force: f = (-z*gx, -z*gy), central differences with replicate edges.
// One thread = 4 consecutive pixels (one float4).
__global__ __launch_bounds__(128) void force_k(const float* __restrict__ img,
                                               const float* __restrict__ z) {
    int c = blockIdx.x * blockDim.x + threadIdx.x;   // float4 column 0..255
    int y = blockIdx.y;
    int x0 = c * 4;
    int ym = max(y - 1, 0), yp = min(y + 1, H - 1);

    float4 ic = ((const float4*)(img + y  * W))[c];
    float4 iu = ((const float4*)(img + ym * W))[c];
    float4 id = ((const float4*)(img + yp * W))[c];
    float4 zz = ((const float4*)(z   + y  * W))[c];
    float left  = (x0 > 0)     ? img[y * W + x0 - 1] : ic.x;
    float right = (x0 + 4 < W) ? img[y * W + x0 + 4] : ic.w;

    float4 f0, f1;
    f0.x = -zz.x * 0.5f * (ic.y  - left);
    f0.y = -zz.y * 0.5f * (ic.z  - ic.x);
    f0.z = -zz.z * 0.5f * (ic.w  - ic.y);
    f0.w = -zz.w * 0.5f * (right - ic.z);
    f1.x = -zz.x * 0.5f * (id.x - iu.x);
    f1.y = -zz.y * 0.5f * (id.y - iu.y);
    f1.z = -zz.z * 0.5f * (id.z - iu.z);
    f1.w = -zz.w * 0.5f * (id.w - iu.w);

    ((float4*)g_f[0])[y * W4 + c] = f0;
    ((float4*)g_f[1])[y * W4 + c] = f1;
}

// ---------------------------------------------------------------------------
// vertical blur: one thread = one float4 column x VY rows x 2 channels
__global__ __launch_bounds__(64, 4) void vblur_k() {
    int c  = blockIdx.x * blockDim.x + threadIdx.x;  // float4 column 0..255
    int y0 = blockIdx.y * VY;

    const float4* __restrict__ f0p = (const float4*)g_f[0];
    const float4* __restrict__ f1p = (const float4*)g_f[1];

    float4 a0[VY], a1[VY];
#pragma unroll
    for (int o = 0; o < VY; o++) {
        a0[o] = make_float4(0.f, 0.f, 0.f, 0.f);
        a1[o] = make_float4(0.f, 0.f, 0.f, 0.f);
    }

#pragma unroll
    for (int j = 0; j < KS + VY - 1; j++) {      // input rows y0-R+j
        int yy = y0 - R + j;
        yy = max(0, min(H - 1, yy));
        float4 f0 = f0p[yy * W4 + c];
        float4 f1 = f1p[yy * W4 + c];
#pragma unroll
        for (int o = 0; o < VY; o++) {
            int tap = j - o;
            if (tap >= 0 && tap < KS) {
                float w = wt(tap);
                fma4(a0[o], w, f0);
                fma4(a1[o], w, f1);
            }
        }
    }
#pragma unroll
    for (int o = 0; o < VY; o++) {
        ((float4*)g_t[0])[(y0 + o) * W4 + c] = a0[o];
        ((float4*)g_t[1])[(y0 + o) * W4 + c] = a1[o];
    }
}

// ---------------------------------------------------------------------------
// horizontal blur: one thread = VX=8 consecutive cols, channels sequential.
// 64-thread blocks, 2 blocks per row (better SM balance / latency hiding).
__global__ __launch_bounds__(64) void hblur_k() {
    int tc = blockIdx.y * 64 + threadIdx.x;   // global column-group 0..127
    int y  = blockIdx.x;                      // one row
    int x0 = tc * VX;

    bool interior = (tc >= 3 && tc <= 124);

#pragma unroll
    for (int ch = 0; ch < 2; ch++) {
        const float* __restrict__ row = g_t[ch] + y * W;
        float a[VX];
#pragma unroll
        for (int o = 0; o < VX; o++) a[o] = 0.f;

        if (interior) {
            // inputs needed: [x0-18, x0+25]; aligned window [x0-20, x0+28)
            const float4* r = (const float4*)(row + x0 - 20);
#pragma unroll
            for (int c4 = 0; c4 < 12; c4++) {
                float4 q = r[c4];
#pragma unroll
                for (int e = 0; e < 4; e++) {
                    int j = c4 * 4 + e;            // input x = x0-20+j
                    float v = get4(q, e);
#pragma unroll
                    for (int o = 0; o < VX; o++) {
                        int tap = j - 2 - o;        // (x0-20+j) - (x0+o-18)
                        if (tap >= 0 && tap < KS) a[o] += wt(tap) * v;
                    }
                }
            }
        } else {
#pragma unroll
            for (int j = 0; j < KS + VX - 1; j++) { // input x = x0-R+j
                int xx = x0 - R + j;
                xx = max(0, min(W - 1, xx));
                float v = row[xx];
#pragma unroll
                for (int o = 0; o < VX; o++) {
                    int tap = j - o;
                    if (tap >= 0 && tap < KS) a[o] += wt(tap) * v;
                }
            }
        }
        // v = smooth * (RHO/MU), RHO=MU=1
        float4* dst = (float4*)(g_v[ch] + y * W + x0);
        dst[0] = make_float4(a[0], a[1], a[2], a[3]);
        dst[1] = make_float4(a[4], a[5], a[6], a[7]);
    }
}

// ---------------------------------------------------------------------------
// bilinear sample with border clamping (map_coordinates order=1 mode='nearest')
__device__ __forceinline__ float bilin(const float* __restrict__ a,
                                       float cy, float cx) {
    float fy = floorf(cy), fx = floorf(cx);
    float wy = cy - fy,    wx = cx - fx;
    int y0 = (int)fy, x0 = (int)fx;
    int y0c = min(max(y0, 0), H - 1);
    int y1c = min(max(y0 + 1, 0), H - 1);
    int x0c = min(max(x0, 0), W - 1);
    int x1c = min(max(x0 + 1, 0), W - 1);
    float a00 = a[y0c * W + x0c], a01 = a[y0c * W + x1c];
    float a10 = a[y1c * W + x0c], a11 = a[y1c * W + x1c];
    float t0 = a00 + wx * (a01 - a00);
    float t1 = a10 + wx * (a11 - a10);
    return t0 + wy * (t1 - t0);
}

// divergence + semi-Lagrangian update; 1 pixel per thread (gather coalescing:
// adjacent lanes gather adjacent pixels -> 1-2 L1 lines per warp load).
__global__ __launch_bounds__(256) void advect_k(const float* __restrict__ zc,
                                                const float* __restrict__ ic,
                                                float* __restrict__ zout,
                                                float* __restrict__ iout) {
    int x = blockIdx.x * blockDim.x + threadIdx.x;
    int y = blockIdx.y;
    int i = y * W + x;

    const float* __restrict__ vx = g_v[0];
    const float* __restrict__ vy = g_v[1];
    int xm = max(x - 1, 0), xp = min(x + 1, W - 1);
    int ym = max(y - 1, 0), yp = min(y + 1, H - 1);

    float dvx_dx = 0.5f * (vx[y * W + xp] - vx[y * W + xm]);
    float dvy_dy = 0.5f * (vy[yp * W + x] - vy[ym * W + x]);
    float div    = dvx_dx + dvy_dy;

    float cy = (float)y - vy[i] * INV_N;
    float cx = (float)x - vx[i] * INV_N;

    float zold = zc[i];
    float znew = bilin(zc, cy, cx) - zold * div * INV_N;
    float inew = bilin(ic, cy, cx) + znew * INV_N;   // * MU / N, MU = 1

    zout[i] = znew;
    iout[i] = inew;
}

// ---------------------------------------------------------------------------
extern "C" void kernel_launch(void* const* d_in, const int* in_sizes, int n_in,
                              void* d_out, int out_size) {
    const float* image = (const float*)d_in[0];
    const float* resid = (const float*)d_in[1];

    void* p_img = nullptr; void* p_z = nullptr;
    cudaGetSymbolAddress(&p_img, g_img);
    cudaGetSymbolAddress(&p_z, g_z);
    float* imgbuf[2] = {(float*)p_img, (float*)p_img + H * W};
    float* zbuf[2]   = {(float*)p_z,   (float*)p_z   + H * W};

    for (int s = 0; s < NSTEP; s++) {
        const float* ic = (s == 0) ? image : imgbuf[s & 1];
        const float* zc = (s == 0) ? resid : zbuf[s & 1];
        float* iout = (s == NSTEP - 1) ? (float*)d_out : imgbuf[(s + 1) & 1];
        float* zout = zbuf[(s + 1) & 1];

        force_k<<<dim3(W4 / 128, H), 128>>>(ic, zc);
        vblur_k<<<dim3(W4 / 64, H / VY), 64>>>();
        hblur_k<<<dim3(H, 2), 64>>>();
        advect_k<<<dim3(W / 256, H), 256>>>(zc, ic, zout, iout);
    }
}

// round 9
// speedup vs baseline: 1.1456x; 1.0066x over previous
#include <cuda_runtime.h>
#include <math.h>

#define H 1024
#define W 1024
#define R 18
#define KS 37           // 2*R+1
#define NSTEP 16
#define VY 8            // output rows per thread in vertical blur
#define VX 8            // output cols per thread in horizontal blur
#define W4 (W/4)
#define INV_N (1.0f/16.0f)

// Persistent scratch (device globals: allowed; no runtime allocation)
__device__ float g_img[2][H*W];
__device__ float g_z[2][H*W];
__device__ float g_f[2][H*W];   // force: fx = -z*gx, fy = -z*gy
__device__ float g_t[2][H*W];   // after vertical blur
__device__ float g_v[2][H*W];   // velocity (vx, vy)

// ---------------------------------------------------------------------------
// Gaussian weights (sigma=6, radius 18), normalized; literals -> FFMA-imm.
__device__ __forceinline__ float wt(int i) {
    int d = i < R ? R - i : i - R;
    switch (d) {
        case 0:  return 0.066625152f;
        case 1:  return 0.065706198f;
        case 2:  return 0.063024692f;
        case 3:  return 0.058796492f;
        case 4:  return 0.053349252f;
        case 5:  return 0.047080544f;
        case 6:  return 0.040410194f;
        case 7:  return 0.033734705f;
        case 8:  return 0.027390419f;
        case 9:  return 0.021630020f;
        case 10: return 0.016613128f;
        case 11: return 0.012410281f;
        case 12: return 0.009016734f;
        case 13: return 0.006371659f;
        case 14: return 0.004379178f;
        case 15: return 0.002927305f;
        case 16: return 0.001903181f;
        case 17: return 0.001203452f;
        case 18: return 0.000740139f;
    }
    return 0.f;
}

__device__ __forceinline__ void fma4(float4& a, float w, const float4& v) {
    a.x += w * v.x; a.y += w * v.y; a.z += w * v.z; a.w += w * v.w;
}
__device__ __forceinline__ float get4(const float4& q, int e) {
    return e == 0 ? q.x : e == 1 ? q.y : e == 2 ? q.z : q.w;
}

// ---------------------------------------------------------------------------
// force: f = (-z*gx, -z*gy), central differences with replicate edges.
// One thread = 4 consecutive pixels (one float4).
__global__ __launch_bounds__(128) void force_k(const float* __restrict__ img,
                                               const float* __restrict__ z) {
    int c = blockIdx.x * blockDim.x + threadIdx.x;   // float4 column 0..255
    int y = blockIdx.y;
    int x0 = c * 4;
    int ym = max(y - 1, 0), yp = min(y + 1, H - 1);

    float4 ic = ((const float4*)(img + y  * W))[c];
    float4 iu = ((const float4*)(img + ym * W))[c];
    float4 id = ((const float4*)(img + yp * W))[c];
    float4 zz = ((const float4*)(z   + y  * W))[c];
    float left  = (x0 > 0)     ? img[y * W + x0 - 1] : ic.x;
    float right = (x0 + 4 < W) ? img[y * W + x0 + 4] : ic.w;

    float4 f0, f1;
    f0.x = -zz.x * 0.5f * (ic.y  - left);
    f0.y = -zz.y * 0.5f * (ic.z  - ic.x);
    f0.z = -zz.z * 0.5f * (ic.w  - ic.y);
    f0.w = -zz.w * 0.5f * (right - ic.z);
    f1.x = -zz.x * 0.5f * (id.x - iu.x);
    f1.y = -zz.y * 0.5f * (id.y - iu.y);
    f1.z = -zz.z * 0.5f * (id.z - iu.z);
    f1.w = -zz.w * 0.5f * (id.w - iu.w);

    ((float4*)g_f[0])[y * W4 + c] = f0;
    ((float4*)g_f[1])[y * W4 + c] = f1;
}

// ---------------------------------------------------------------------------
// vertical blur: one thread = one float4 column x VY rows x 2 channels
__global__ __launch_bounds__(64, 4) void vblur_k() {
    int c  = blockIdx.x * blockDim.x + threadIdx.x;  // float4 column 0..255
    int y0 = blockIdx.y * VY;

    const float4* __restrict__ f0p = (const float4*)g_f[0];
    const float4* __restrict__ f1p = (const float4*)g_f[1];

    float4 a0[VY], a1[VY];
#pragma unroll
    for (int o = 0; o < VY; o++) {
        a0[o] = make_float4(0.f, 0.f, 0.f, 0.f);
        a1[o] = make_float4(0.f, 0.f, 0.f, 0.f);
    }

#pragma unroll
    for (int j = 0; j < KS + VY - 1; j++) {      // input rows y0-R+j
        int yy = y0 - R + j;
        yy = max(0, min(H - 1, yy));
        float4 f0 = f0p[yy * W4 + c];
        float4 f1 = f1p[yy * W4 + c];
#pragma unroll
        for (int o = 0; o < VY; o++) {
            int tap = j - o;
            if (tap >= 0 && tap < KS) {
                float w = wt(tap);
                fma4(a0[o], w, f0);
                fma4(a1[o], w, f1);
            }
        }
    }
#pragma unroll
    for (int o = 0; o < VY; o++) {
        ((float4*)g_t[0])[(y0 + o) * W4 + c] = a0[o];
        ((float4*)g_t[1])[(y0 + o) * W4 + c] = a1[o];
    }
}

// ---------------------------------------------------------------------------
// horizontal blur: one thread = VX=8 consecutive cols, channels sequential.
// 64-thread blocks, 2 blocks per row (better SM balance / latency hiding).
__global__ __launch_bounds__(64) void hblur_k() {
    int tc = blockIdx.y * 64 + threadIdx.x;   // global column-group 0..127
    int y  = blockIdx.x;                      // one row
    int x0 = tc * VX;

    bool interior = (tc >= 3 && tc <= 124);

#pragma unroll
    for (int ch = 0; ch < 2; ch++) {
        const float* __restrict__ row = g_t[ch] + y * W;
        float a[VX];
#pragma unroll
        for (int o = 0; o < VX; o++) a[o] = 0.f;

        if (interior) {
            // inputs needed: [x0-18, x0+25]; aligned window [x0-20, x0+28)
            const float4* r = (const float4*)(row + x0 - 20);
#pragma unroll
            for (int c4 = 0; c4 < 12; c4++) {
                float4 q = r[c4];
#pragma unroll
                for (int e = 0; e < 4; e++) {
                    int j = c4 * 4 + e;            // input x = x0-20+j
                    float v = get4(q, e);
#pragma unroll
                    for (int o = 0; o < VX; o++) {
                        int tap = j - 2 - o;        // (x0-20+j) - (x0+o-18)
                        if (tap >= 0 && tap < KS) a[o] += wt(tap) * v;
                    }
                }
            }
        } else {
#pragma unroll
            for (int j = 0; j < KS + VX - 1; j++) { // input x = x0-R+j
                int xx = x0 - R + j;
                xx = max(0, min(W - 1, xx));
                float v = row[xx];
#pragma unroll
                for (int o = 0; o < VX; o++) {
                    int tap = j - o;
                    if (tap >= 0 && tap < KS) a[o] += wt(tap) * v;
                }
            }
        }
        // v = smooth * (RHO/MU), RHO=MU=1
        float4* dst = (float4*)(g_v[ch] + y * W + x0);
        dst[0] = make_float4(a[0], a[1], a[2], a[3]);
        dst[1] = make_float4(a[4], a[5], a[6], a[7]);
    }
}

// ---------------------------------------------------------------------------
// Bilinear sample of both fields with *coordinate* pre-clamping.
// Pre-clamping (cy,cx) into [0,H-1]x[0,W-1] before floor is exactly
// equivalent to per-corner index clamping for mode='nearest':
//   cy < 0   -> orig: both rows clamp to 0, weights mix row0 with row0 = row0;
//               pre-clamp: cy=0, wy=0 -> row0. identical. (same above H-1 / x)
__device__ __forceinline__ void bilin_zi(const float* __restrict__ z,
                                         const float* __restrict__ im,
                                         float cy, float cx,
                                         float& zr, float& ir) {
    cy = fminf(fmaxf(cy, 0.f), (float)(H - 1));
    cx = fminf(fmaxf(cx, 0.f), (float)(W - 1));
    float fy = floorf(cy), fx = floorf(cx);
    float wy = cy - fy,    wx = cx - fx;
    int y0 = (int)fy, x0 = (int)fx;
    int dx  = (x0 < W - 1) ? 1 : 0;
    int dyW = (y0 < H - 1) ? W : 0;
    int b   = y0 * W + x0;

    float z00 = z[b],        z01 = z[b + dx];
    float z10 = z[b + dyW],  z11 = z[b + dyW + dx];
    float i00 = im[b],       i01 = im[b + dx];
    float i10 = im[b + dyW], i11 = im[b + dyW + dx];

    float zt0 = z00 + wx * (z01 - z00);
    float zt1 = z10 + wx * (z11 - z10);
    zr = zt0 + wy * (zt1 - zt0);
    float it0 = i00 + wx * (i01 - i00);
    float it1 = i10 + wx * (i11 - i10);
    ir = it0 + wy * (it1 - it0);
}

// divergence + semi-Lagrangian update; 2 rows per thread (2 independent
// gather chains per thread for latency hiding; vy column shared).
__global__ __launch_bounds__(256) void advect_k(const float* __restrict__ zc,
                                                const float* __restrict__ ic,
                                                float* __restrict__ zout,
                                                float* __restrict__ iout) {
    int x   = blockIdx.x * blockDim.x + threadIdx.x;
    int y0r = blockIdx.y * 2;

    const float* __restrict__ vx = g_v[0];
    const float* __restrict__ vy = g_v[1];
    int xm = max(x - 1, 0), xp = min(x + 1, W - 1);
    int ya = max(y0r - 1, 0), yb = min(y0r + 2, H - 1);

    // vy column: rows y0r-1 .. y0r+2 (4 loads serve both rows)
    float vy_m = vy[ya * W + x];
    float vy_0 = vy[y0r * W + x];
    float vy_1 = vy[(y0r + 1) * W + x];
    float vy_p = vy[yb * W + x];

#pragma unroll
    for (int r = 0; r < 2; r++) {
        int y = y0r + r;
        int i = y * W + x;
        float vxc = vx[i];
        float vxm = vx[y * W + xm];
        float vxp = vx[y * W + xp];
        float vyc   = r ? vy_1 : vy_0;
        float vy_up = r ? vy_0 : vy_m;
        float vy_dn = r ? vy_p : vy_1;

        float div = 0.5f * (vxp - vxm) + 0.5f * (vy_dn - vy_up);

        float cy = (float)y - vyc * INV_N;
        float cx = (float)x - vxc * INV_N;

        float zw, iw;
        bilin_zi(zc, ic, cy, cx, zw, iw);

        float zold = zc[i];
        float znew = zw - zold * div * INV_N;
        float inew = iw + znew * INV_N;     // * MU / N, MU = 1

        zout[i] = znew;
        iout[i] = inew;
    }
}

// ---------------------------------------------------------------------------
extern "C" void kernel_launch(void* const* d_in, const int* in_sizes, int n_in,
                              void* d_out, int out_size) {
    const float* image = (const float*)d_in[0];
    const float* resid = (const float*)d_in[1];

    void* p_img = nullptr; void* p_z = nullptr;
    cudaGetSymbolAddress(&p_img, g_img);
    cudaGetSymbolAddress(&p_z, g_z);
    float* imgbuf[2] = {(float*)p_img, (float*)p_img + H * W};
    float* zbuf[2]   = {(float*)p_z,   (float*)p_z   + H * W};

    for (int s = 0; s < NSTEP; s++) {
        const float* ic = (s == 0) ? image : imgbuf[s & 1];
        const float* zc = (s == 0) ? resid : zbuf[s & 1];
        float* iout = (s == NSTEP - 1) ? (float*)d_out : imgbuf[(s + 1) & 1];
        float* zout = zbuf[(s + 1) & 1];

        force_k<<<dim3(W4 / 128, H), 128>>>(ic, zc);
        vblur_k<<<dim3(W4 / 64, H / VY), 64>>>();
        hblur_k<<<dim3(H, 2), 64>>>();
        advect_k<<<dim3(W / 256, H / 2), 256>>>(zc, ic, zout, iout);
    }
}